// round 3
// baseline (speedup 1.0000x reference)
#include <cuda_runtime.h>
#include <cuda_fp16.h>
#include <cstdint>

#define NN 50000
#define F  256
#define KW 3
#define EMAX 1600000

// Scratch (no cudaMalloc allowed).
__device__ __half g_xh[(size_t)NN * F];
__device__ __half g_T1[(size_t)NN * F];
__device__ __half g_T2[(size_t)NN * F];
__device__ __half g_wh[(size_t)KW * F * F];
__device__ int2   g_ep[EMAX];          // packed (col, w-bits)
__device__ int    g_rp[NN + 1];

// ---------------------------------------------------------------------------
// row_ptr: lower_bound of each node id in the sorted edge_row array.
// ---------------------------------------------------------------------------
__global__ void build_rowptr_kernel(const int* __restrict__ erow, int E, int N) {
    int i = blockIdx.x * blockDim.x + threadIdx.x;
    if (i > N) return;
    int lo = 0, hi = E;
    while (lo < hi) {
        int mid = (lo + hi) >> 1;
        if (erow[mid] < i) lo = mid + 1; else hi = mid;
    }
    g_rp[i] = lo;
}

// ---------------------------------------------------------------------------
// Pack edges: (col, w) -> int2 so SpMM reads one 8B broadcast per edge.
// ---------------------------------------------------------------------------
__global__ void pack_edges_kernel(const int* __restrict__ ecol,
                                  const float* __restrict__ ew, int E) {
    int i = blockIdx.x * blockDim.x + threadIdx.x;
    if (i < E) g_ep[i] = make_int2(ecol[i], __float_as_int(ew[i]));
}

// ---------------------------------------------------------------------------
// fp32 -> fp16 (RN, unbiased)
// ---------------------------------------------------------------------------
__global__ void cvt_kernel(const float* __restrict__ src, __half* __restrict__ dst, int n4) {
    int i = blockIdx.x * blockDim.x + threadIdx.x;
    if (i >= n4) return;
    float4 v = *reinterpret_cast<const float4*>(src + (size_t)i * 4);
    __half2 h0 = __floats2half2_rn(v.x, v.y);
    __half2 h1 = __floats2half2_rn(v.z, v.w);
    uint2 o;
    o.x = *reinterpret_cast<uint32_t*>(&h0);
    o.y = *reinterpret_cast<uint32_t*>(&h1);
    *reinterpret_cast<uint2*>(dst + (size_t)i * 4) = o;
}

// ---------------------------------------------------------------------------
// SpMM: warp per node row. Lane l owns features [8l, 8l+8) as one uint4
// (8 fp16). Edge (col,w) read as broadcast int2; gathers batched x8 for MLP.
// MODE 0: g_T1 = L @ g_xh        MODE 1: g_T2 = 2*(L @ g_T1) - g_xh
// ---------------------------------------------------------------------------
__device__ __forceinline__ void accum8(float acc[8], uint4 v, float w) {
    const __half2* h = reinterpret_cast<const __half2*>(&v);
    #pragma unroll
    for (int q = 0; q < 4; ++q) {
        float2 f = __half22float2(h[q]);
        acc[2 * q]     = fmaf(w, f.x, acc[2 * q]);
        acc[2 * q + 1] = fmaf(w, f.y, acc[2 * q + 1]);
    }
}

template <int MODE>
__global__ __launch_bounds__(256)
void spmm_h_kernel() {
    int warp = threadIdx.x >> 5, lane = threadIdx.x & 31;
    int node = blockIdx.x * 8 + warp;
    if (node >= NN) return;

    const uint4* __restrict__ src =
        reinterpret_cast<const uint4*>((MODE == 0) ? g_xh : g_T1);
    __half* dst = (MODE == 0) ? g_T1 : g_T2;

    int r0 = g_rp[node], r1 = g_rp[node + 1];
    float acc[8];
    #pragma unroll
    for (int q = 0; q < 8; ++q) acc[q] = 0.f;

    int j = r0;
    for (; j + 8 <= r1; j += 8) {
        int2 e[8];
        #pragma unroll
        for (int u = 0; u < 8; ++u) e[u] = __ldg(&g_ep[j + u]);
        uint4 v[8];
        #pragma unroll
        for (int u = 0; u < 8; ++u)
            v[u] = __ldg(&src[(size_t)e[u].x * 32 + lane]);
        #pragma unroll
        for (int u = 0; u < 8; ++u)
            accum8(acc, v[u], __int_as_float(e[u].y));
    }
    for (; j < r1; ++j) {
        int2 e = __ldg(&g_ep[j]);
        uint4 v = __ldg(&src[(size_t)e.x * 32 + lane]);
        accum8(acc, v, __int_as_float(e.y));
    }

    if (MODE == 1) {
        uint4 xv = reinterpret_cast<const uint4*>(g_xh)[(size_t)node * 32 + lane];
        const __half2* h = reinterpret_cast<const __half2*>(&xv);
        #pragma unroll
        for (int q = 0; q < 4; ++q) {
            float2 f = __half22float2(h[q]);
            acc[2 * q]     = 2.f * acc[2 * q]     - f.x;
            acc[2 * q + 1] = 2.f * acc[2 * q + 1] - f.y;
        }
    }

    __half2 o[4];
    #pragma unroll
    for (int q = 0; q < 4; ++q) o[q] = __floats2half2_rn(acc[2 * q], acc[2 * q + 1]);
    reinterpret_cast<uint4*>(dst)[(size_t)node * 32 + lane] =
        *reinterpret_cast<uint4*>(o);
}

// ---------------------------------------------------------------------------
// GEMM: out[N,256] = [xh | T1 | T2](N x 768) @ Wh(768 x 256) + bias
// fp16 mma m16n8k16 (fp32 accum), cp.async double-buffered, BM=BN=128 BK=32.
// grid(2, 391): both column-blocks of a row-tile land in the same wave ->
// the second reads A from L2 instead of DRAM.
// ---------------------------------------------------------------------------
#define GBM 128
#define GBN 128
#define GBK 32
#define PA  40
#define PB  136

__device__ __forceinline__ void cp16(uint32_t dst, const void* src, int sz) {
    asm volatile("cp.async.cg.shared.global [%0], [%1], 16, %2;\n"
                 :: "r"(dst), "l"(src), "r"(sz));
}
__device__ __forceinline__ void ldsm_x4(uint32_t r[4], uint32_t addr) {
    asm volatile("ldmatrix.sync.aligned.m8n8.x4.shared.b16 {%0,%1,%2,%3}, [%4];"
                 : "=r"(r[0]), "=r"(r[1]), "=r"(r[2]), "=r"(r[3]) : "r"(addr));
}
__device__ __forceinline__ void ldsm_x4_t(uint32_t r[4], uint32_t addr) {
    asm volatile("ldmatrix.sync.aligned.m8n8.x4.trans.shared.b16 {%0,%1,%2,%3}, [%4];"
                 : "=r"(r[0]), "=r"(r[1]), "=r"(r[2]), "=r"(r[3]) : "r"(addr));
}

__global__ __launch_bounds__(256, 2)
void gemm_h_kernel(const float* __restrict__ bias, float* __restrict__ out, int N) {
    __shared__ __half sA[2][GBM * PA];
    __shared__ __half sB[2][GBK * PB];

    int tid  = threadIdx.x;
    int warp = tid >> 5, lane = tid & 31;
    int row0 = blockIdx.y * GBM, col0 = blockIdx.x * GBN;   // swapped mapping
    int wm = (warp >> 1) * 32;
    int wn = (warp & 1) * 64;

    float acc[2][8][4];
    #pragma unroll
    for (int mi = 0; mi < 2; ++mi)
        #pragma unroll
        for (int ni = 0; ni < 8; ++ni)
            #pragma unroll
            for (int q = 0; q < 4; ++q) acc[mi][ni][q] = 0.f;

    uint32_t aBase = (uint32_t)__cvta_generic_to_shared(&sA[0][0]);
    uint32_t bBase = (uint32_t)__cvta_generic_to_shared(&sB[0][0]);
    const uint32_t aStage = GBM * PA * 2;
    const uint32_t bStage = GBK * PB * 2;

    auto issue = [&](int s, int iter) {
        const __half* asrc = (iter < 8) ? g_xh : (iter < 16) ? g_T1 : g_T2;
        int colA = (iter * GBK) & 255;
        #pragma unroll
        for (int it = 0; it < 2; ++it) {
            int idx = tid + it * 256;
            int r = idx >> 2, c = idx & 3;
            int grow = row0 + r;
            const __half* g = asrc + (size_t)min(grow, NN - 1) * 256 + colA + c * 8;
            cp16(aBase + s * aStage + (uint32_t)(r * PA + c * 8) * 2, g,
                 grow < N ? 16 : 0);
        }
        int kb = iter * GBK;
        #pragma unroll
        for (int it = 0; it < 2; ++it) {
            int idx = tid + it * 256;
            int k = idx >> 4, c = idx & 15;
            const __half* g = g_wh + (size_t)(kb + k) * 256 + col0 + c * 8;
            cp16(bBase + s * bStage + (uint32_t)(k * PB + c * 8) * 2, g, 16);
        }
    };

    issue(0, 0);
    asm volatile("cp.async.commit_group;");

    for (int iter = 0; iter < 24; ++iter) {
        int s = iter & 1;
        if (iter + 1 < 24) {
            issue(s ^ 1, iter + 1);
            asm volatile("cp.async.commit_group;");
            asm volatile("cp.async.wait_group 1;");
        } else {
            asm volatile("cp.async.wait_group 0;");
        }
        __syncthreads();

        uint32_t aS = aBase + s * aStage;
        uint32_t bS = bBase + s * bStage;
        #pragma unroll
        for (int kc = 0; kc < 2; ++kc) {
            uint32_t a[2][4], b[4][4];
            #pragma unroll
            for (int mi = 0; mi < 2; ++mi) {
                int r = wm + mi * 16 + (lane & 15);
                ldsm_x4(a[mi], aS + (uint32_t)(r * PA + kc * 16 + (lane >> 4) * 8) * 2);
            }
            #pragma unroll
            for (int bi = 0; bi < 4; ++bi) {
                int k = kc * 16 + (lane & 15);
                ldsm_x4_t(b[bi], bS + (uint32_t)(k * PB + wn + bi * 16 + (lane >> 4) * 8) * 2);
            }
            #pragma unroll
            for (int mi = 0; mi < 2; ++mi)
                #pragma unroll
                for (int ni = 0; ni < 8; ++ni) {
                    uint32_t b0 = b[ni >> 1][(ni & 1) * 2];
                    uint32_t b1 = b[ni >> 1][(ni & 1) * 2 + 1];
                    asm volatile(
                        "mma.sync.aligned.m16n8k16.row.col.f32.f16.f16.f32 "
                        "{%0,%1,%2,%3}, {%4,%5,%6,%7}, {%8,%9}, {%0,%1,%2,%3};"
                        : "+f"(acc[mi][ni][0]), "+f"(acc[mi][ni][1]),
                          "+f"(acc[mi][ni][2]), "+f"(acc[mi][ni][3])
                        : "r"(a[mi][0]), "r"(a[mi][1]), "r"(a[mi][2]), "r"(a[mi][3]),
                          "r"(b0), "r"(b1));
                }
        }
        __syncthreads();
    }

    int g = lane >> 2, t = lane & 3;
    #pragma unroll
    for (int ni = 0; ni < 8; ++ni) {
        int col = col0 + wn + ni * 8 + t * 2;
        float b0 = __ldg(bias + col), b1 = __ldg(bias + col + 1);
        #pragma unroll
        for (int mi = 0; mi < 2; ++mi) {
            int row = row0 + wm + mi * 16 + g;
            if (row < N) {
                float2 v = make_float2(acc[mi][ni][0] + b0, acc[mi][ni][1] + b1);
                *reinterpret_cast<float2*>(out + (size_t)row * 256 + col) = v;
            }
            if (row + 8 < N) {
                float2 v = make_float2(acc[mi][ni][2] + b0, acc[mi][ni][3] + b1);
                *reinterpret_cast<float2*>(out + (size_t)(row + 8) * 256 + col) = v;
            }
        }
    }
}

// ---------------------------------------------------------------------------
extern "C" void kernel_launch(void* const* d_in, const int* in_sizes, int n_in,
                              void* d_out, int out_size) {
    const float* x    = (const float*)d_in[0];
    const int*   erow = (const int*)  d_in[1];
    const int*   ecol = (const int*)  d_in[2];
    const float* ew   = (const float*)d_in[3];
    const float* wgt  = (const float*)d_in[4];
    const float* bias = (const float*)d_in[5];
    float* out = (float*)d_out;

    int N = in_sizes[0] / F;   // 50000
    int E = in_sizes[1];       // 1600000

    build_rowptr_kernel<<<(N + 1 + 255) / 256, 256>>>(erow, E, N);
    pack_edges_kernel<<<(E + 255) / 256, 256>>>(ecol, ew, E);

    __half* xh_p; cudaGetSymbolAddress((void**)&xh_p, g_xh);
    __half* wh_p; cudaGetSymbolAddress((void**)&wh_p, g_wh);
    cvt_kernel<<<(N * F / 4 + 255) / 256, 256>>>(x, xh_p, N * F / 4);
    cvt_kernel<<<(KW * F * F / 4 + 255) / 256, 256>>>(wgt, wh_p, KW * F * F / 4);

    spmm_h_kernel<0><<<(N + 7) / 8, 256>>>();   // T1 = L xh
    spmm_h_kernel<1><<<(N + 7) / 8, 256>>>();   // T2 = 2 L T1 - xh

    dim3 grid(F / GBN, (N + GBM - 1) / GBM);    // (2, 391)
    gemm_h_kernel<<<grid, 256>>>(bias, out, N);
}